// round 8
// baseline (speedup 1.0000x reference)
#include <cuda_runtime.h>
#include <math.h>

typedef unsigned long long ull;
struct u2v { ull x, y; };

#define THREADS 768
#define SPB 24
#define NPAIR 12
#define KT 120

// X region (floats): conv wts -> FC1 tiles -> reduction scratch(ull) -> head wts
#define W1_OFF  0
#define B1_OFF  432
#define W2_OFF  448      // 32*145
#define B2C_OFF 5088
#define W3_OFF  5120     // 64*289
#define B3_OFF  23616
#define X_FLOATS 23680
#define X_BYTES (X_FLOATS * 4)             // 94720

#define PAIR_ST 592
#define A_ULL (NPAIR * PAIR_ST)
#define A_BYTES (A_ULL * 8)                // 56832
#define B_ULL (NPAIR * 320)
#define B_BYTES (B_ULL * 8)                // 30720
#define SMEM_BYTES (X_BYTES + A_BYTES + B_BYTES)   // 182272

// B-region ull offsets after convs
#define T1O 0                    // 12*128
#define T2O (NPAIR * 128)        // 12*66
#define C1O (T2O + NPAIR * 66)   // 12*66  (ends 3120 <= 3840)

// head weights in X floats
#define W2S  0
#define W3S  8192
#define B2SH 8320
#define B3SH 8384
#define CW2S 8386
#define CB2S 8450

__device__ __forceinline__ ull dup2(float w) {
    ull r; unsigned u = __float_as_uint(w);
    asm("mov.b64 %0, {%1, %1};" : "=l"(r) : "r"(u));
    return r;
}
__device__ __forceinline__ ull pk(float lo, float hi) {
    ull r;
    asm("mov.b64 %0, {%1, %2};" : "=l"(r)
        : "r"(__float_as_uint(lo)), "r"(__float_as_uint(hi)));
    return r;
}
__device__ __forceinline__ void unpk(ull v, float& lo, float& hi) {
    unsigned a, b;
    asm("mov.b64 {%0, %1}, %2;" : "=r"(a), "=r"(b) : "l"(v));
    lo = __uint_as_float(a); hi = __uint_as_float(b);
}
__device__ __forceinline__ void ffma2(ull& d, ull a, ull b) {
    asm("fma.rn.f32x2 %0, %1, %2, %0;" : "+l"(d) : "l"(a), "l"(b));
}
__device__ __forceinline__ ull fadd2(ull a, ull b) {
    ull r;
    asm("add.rn.f32x2 %0, %1, %2;" : "=l"(r) : "l"(a), "l"(b));
    return r;
}
__device__ __forceinline__ ull relu2(ull v) {
    float lo, hi; unpk(v, lo, hi);
    return pk(fmaxf(lo, 0.f), fmaxf(hi, 0.f));
}
__device__ __forceinline__ void bar_pair(int pair) {
    asm volatile("bar.sync %0, 64;" :: "r"(pair + 1) : "memory");
}

// conv1: out rows YB..YB+2 for channel co
template<int YB>
__device__ __forceinline__ void conv1_half(const float* cw, const ull* Bw,
                                           ull* Aw, int co) {
    ull acc[18];
    ull bb = dup2(cw[B1_OFF + co]);
    #pragma unroll
    for (int p = 0; p < 18; p++) acc[p] = bb;
    const float* wr = cw + W1_OFF + co*27;
    #pragma unroll
    for (int ci = 0; ci < 3; ci++) {
        ull wd[9];
        #pragma unroll
        for (int t = 0; t < 9; t++) wd[t] = dup2(wr[ci*9 + t]);
        #pragma unroll
        for (int iy = YB - 1; iy <= YB + 3; iy++) {
            if (iy < 0 || iy > 5) continue;
            ull r[6];
            u2v v0 = *(const u2v*)(Bw + ci*36 + iy*6 + 0);
            u2v v1 = *(const u2v*)(Bw + ci*36 + iy*6 + 2);
            u2v v2 = *(const u2v*)(Bw + ci*36 + iy*6 + 4);
            r[0]=v0.x; r[1]=v0.y; r[2]=v1.x; r[3]=v1.y; r[4]=v2.x; r[5]=v2.y;
            #pragma unroll
            for (int dy = 0; dy < 3; dy++) {
                int y = iy + 1 - dy;
                if (y < YB || y > YB + 2) continue;
                #pragma unroll
                for (int dx = 0; dx < 3; dx++)
                    #pragma unroll
                    for (int x = 0; x < 6; x++) {
                        int xx = x + dx - 1;
                        if (xx < 0 || xx > 5) continue;
                        ffma2(acc[(y - YB)*6 + x], wd[dy*3 + dx], r[xx]);
                    }
            }
        }
    }
    #pragma unroll
    for (int ly = 0; ly < 3; ly++)
        #pragma unroll
        for (int x = 0; x < 6; x++)
            Aw[co*36 + (YB + ly)*6 + x] = relu2(acc[ly*6 + x]);
}

// conv2 rows H*3..H*3+2 for out channel lane (all 32 co); acc[ly*6+x]
template<int H>
__device__ __forceinline__ void conv2_rows(const float* cw, const ull* Aw,
                                           ull* acc, int lane) {
    constexpr int YB = H * 3;
    constexpr int IY0 = (YB - 1 < 0) ? 0 : YB - 1;
    constexpr int IY1 = (YB + 3 > 5) ? 5 : YB + 3;
    ull bb = dup2(cw[B2C_OFF + lane]);
    #pragma unroll
    for (int p = 0; p < 18; p++) acc[p] = bb;
    const float* w2 = cw + W2_OFF + lane*145;
    for (int ci = 0; ci < 16; ci++) {
        ull wd[9];
        #pragma unroll
        for (int t = 0; t < 9; t++) wd[t] = dup2(w2[ci*9 + t]);
        #pragma unroll
        for (int iy = IY0; iy <= IY1; iy++) {
            ull r[6];
            u2v v0 = *(const u2v*)(Aw + ci*36 + iy*6 + 0);
            u2v v1 = *(const u2v*)(Aw + ci*36 + iy*6 + 2);
            u2v v2 = *(const u2v*)(Aw + ci*36 + iy*6 + 4);
            r[0]=v0.x; r[1]=v0.y; r[2]=v1.x; r[3]=v1.y; r[4]=v2.x; r[5]=v2.y;
            #pragma unroll
            for (int dy = 0; dy < 3; dy++) {
                int y = iy + 1 - dy;
                if (y < YB || y > YB + 2) continue;
                #pragma unroll
                for (int dx = 0; dx < 3; dx++) {
                    #pragma unroll
                    for (int x = 0; x < 6; x++) {
                        int xx = x + dx - 1;
                        if (xx < 0 || xx > 5) continue;
                        ffma2(acc[(y - YB)*6 + x], wd[dy*3 + dx], r[xx]);
                    }
                }
            }
        }
    }
}

__global__ void __launch_bounds__(THREADS, 1)
cqcnn_kernel(const float* __restrict__ gin,
             const float* __restrict__ c1w, const float* __restrict__ c1b,
             const float* __restrict__ c2w, const float* __restrict__ c2b,
             const float* __restrict__ c3w, const float* __restrict__ c3b,
             const float* __restrict__ qp,
             const float* __restrict__ ptw1, const float* __restrict__ ptb1,
             const float* __restrict__ ptw2, const float* __restrict__ ptb2,
             const float* __restrict__ ptw3, const float* __restrict__ ptb3,
             const float* __restrict__ cfw1, const float* __restrict__ cfb1,
             const float* __restrict__ cfw2, const float* __restrict__ cfb2,
             float* __restrict__ gout, int nsamp)
{
    extern __shared__ unsigned char smem[];
    float* cw = (float*)smem;                      // X
    ull*  Au  = (ull*)(smem + X_BYTES);            // A: per-pair feats
    ull*  Bu  = (ull*)(smem + X_BYTES + A_BYTES);  // B
    ull*  Xu  = (ull*)smem;                        // X as ull scratch

    const int tid  = threadIdx.x;
    const int wid  = tid >> 5;
    const int lane = tid & 31;
    const int pair = wid >> 1;
    const int h    = wid & 1;

    // ---------- conv weights -> X ----------
    for (int i = tid; i < 16*27;  i += THREADS) cw[W1_OFF + i] = c1w[i];
    for (int i = tid; i < 32*144; i += THREADS)
        cw[W2_OFF + (i/144)*145 + (i%144)] = c2w[i];
    for (int i = tid; i < 64*288; i += THREADS)
        cw[W3_OFF + (i/288)*289 + (i%288)] = c3w[i];
    if (tid < 16) cw[B1_OFF + tid] = c1b[tid];
    else if (tid >= 64  && tid < 96)  cw[B2C_OFF + tid - 64]  = c2b[tid - 64];
    else if (tid >= 128 && tid < 192) cw[B3_OFF  + tid - 128] = c3b[tid - 128];

    // ---------- input load (each warp loads its half of the pair) ----------
    const int s0  = blockIdx.x * SPB + pair * 2;
    const int s0c = min(s0,     nsamp - 1);
    const int s1c = min(s0 + 1, nsamp - 1);
    ull* Bw = Bu + pair * 320;      // input(108), later pooled (32 ch x stride 10)
    ull* Aw = Au + pair * PAIR_ST;  // conv1 acts / feats
    for (int i = lane; i < 54; i += 32) {
        int idx = h*54 + i;
        Bw[idx] = pk(gin[(size_t)s0c * 108 + idx], gin[(size_t)s1c * 108 + idx]);
    }
    __syncthreads();   // weights + inputs visible

    // ---------- conv1 (lanes 0..15) + quantum (h=1 lanes 16..23) ----------
    if (lane < 16) {
        int co = h*8 + (lane >> 1);
        if (lane & 1) conv1_half<3>(cw, Bw, Aw, co);
        else          conv1_half<0>(cw, Bw, Aw, co);
    } else if (h == 1 && lane < 24) {
        int q = lane - 16;
        float xl, xh, nl, nh;
        unpk(Bw[q], xl, xh);
        unpk(Bw[(q + 1) & 7], nl, nh);
        float ql = 0.f, qh = 0.f;
        #pragma unroll
        for (int l = 0; l < 3; l++) {
            float r0 = qp[(l*8 + q)*3 + 0];
            float r1 = qp[(l*8 + q)*3 + 1];
            float r2 = qp[(l*8 + q)*3 + 2];
            ql = sinf(r0*xl) * cosf(r1*nl) + tanhf(r2*ql);
            qh = sinf(r0*xh) * cosf(r1*nh) + tanhf(r2*qh);
        }
        Aw[576 + q] = pk(ql, qh);
    }
    bar_pair(pair);    // conv1 acts complete for this pair

    // ---------- conv2 (row-half per warp) + relu + maxpool ----------
    {
        ull acc[18];
        if (h == 0) conv2_rows<0>(cw, Aw, acc, lane);
        else        conv2_rows<1>(cw, Aw, acc, lane);

        if (h == 0) {
            // pool py0 (rows 0,1) ; partial max of row 2 into py1 slot
            #pragma unroll
            for (int px = 0; px < 3; px++) {
                float a0,b0,a1,b1,a2,b2,a3,b3;
                unpk(acc[0*6 + 2*px  ], a0, b0);
                unpk(acc[0*6 + 2*px+1], a1, b1);
                unpk(acc[1*6 + 2*px  ], a2, b2);
                unpk(acc[1*6 + 2*px+1], a3, b3);
                Bw[lane*10 + px] = pk(
                    fmaxf(fmaxf(fmaxf(a0,a1), fmaxf(a2,a3)), 0.f),
                    fmaxf(fmaxf(fmaxf(b0,b1), fmaxf(b2,b3)), 0.f));
                float p0,q0,p1,q1;
                unpk(acc[2*6 + 2*px  ], p0, q0);
                unpk(acc[2*6 + 2*px+1], p1, q1);
                Bw[lane*10 + 3 + px] = pk(fmaxf(p0,p1), fmaxf(q0,q1));
            }
        }
        bar_pair(pair);   // h0 partials visible
        if (h == 1) {
            // local rows 0,1,2 = global rows 3,4,5
            #pragma unroll
            for (int px = 0; px < 3; px++) {
                float pl, ph;
                unpk(Bw[lane*10 + 3 + px], pl, ph);     // partial from row 2
                float a0,b0,a1,b1;
                unpk(acc[0*6 + 2*px  ], a0, b0);        // row 3
                unpk(acc[0*6 + 2*px+1], a1, b1);
                Bw[lane*10 + 3 + px] = pk(
                    fmaxf(fmaxf(pl, fmaxf(a0,a1)), 0.f),
                    fmaxf(fmaxf(ph, fmaxf(b0,b1)), 0.f));
                float c0,d0,c1,d1,c2,d2,c3,d3;
                unpk(acc[1*6 + 2*px  ], c0, d0);        // rows 4,5
                unpk(acc[1*6 + 2*px+1], c1, d1);
                unpk(acc[2*6 + 2*px  ], c2, d2);
                unpk(acc[2*6 + 2*px+1], c3, d3);
                Bw[lane*10 + 6 + px] = pk(
                    fmaxf(fmaxf(fmaxf(c0,c1), fmaxf(c2,c3)), 0.f),
                    fmaxf(fmaxf(fmaxf(d0,d1), fmaxf(d2,d3)), 0.f));
            }
        }
    }
    bar_pair(pair);   // pooled complete

    // ---------- conv3: 1 co per thread (co = h*32 + lane) -> feats ----------
    {
        int co = h*32 + lane;
        ull acc[9];
        ull bb = dup2(cw[B3_OFF + co]);
        #pragma unroll
        for (int p = 0; p < 9; p++) acc[p] = bb;
        const float* w3 = cw + W3_OFF + co*289;
        for (int ci = 0; ci < 32; ci++) {
            ull r[9];
            u2v v0 = *(const u2v*)(Bw + ci*10 + 0);
            u2v v1 = *(const u2v*)(Bw + ci*10 + 2);
            u2v v2 = *(const u2v*)(Bw + ci*10 + 4);
            u2v v3 = *(const u2v*)(Bw + ci*10 + 6);
            r[0]=v0.x; r[1]=v0.y; r[2]=v1.x; r[3]=v1.y;
            r[4]=v2.x; r[5]=v2.y; r[6]=v3.x; r[7]=v3.y;
            r[8]=Bw[ci*10 + 8];
            #pragma unroll
            for (int t = 0; t < 9; t++) {
                int dy = t/3 - 1, dx = t%3 - 1;
                ull wa = dup2(w3[ci*9 + t]);
                #pragma unroll
                for (int y = 0; y < 3; y++) {
                    int yy = y + dy; if (yy < 0 || yy > 2) continue;
                    #pragma unroll
                    for (int x = 0; x < 3; x++) {
                        int xx = x + dx; if (xx < 0 || xx > 2) continue;
                        ffma2(acc[y*3+x], wa, r[yy*3+xx]);
                    }
                }
            }
        }
        #pragma unroll
        for (int p = 0; p < 9; p++)
            Aw[co*9 + p] = relu2(acc[p]);
    }
    __syncthreads();   // all feats ready for all pairs

    // ---------- FC1: pt1(584->128)+cf1(584->64) ----------
    // thread = og(lane) x sg(warp%3: pairs sg*4..+3) x kc(warp/3: 8-way K split)
    const int og = lane;
    const int sg = (wid % 3);
    const int kc = wid / 3;
    float* wt = cw;                    // [kt][128]
    float* ct = cw + KT*128;           // [kt][64]
    ull a[24];                         // a[j*4+i], j=outs(4 pt + 2 cf), i=pair
    #pragma unroll
    for (int t = 0; t < 24; t++) a[t] = 0ull;

    for (int k0 = 0; k0 < 584; k0 += KT) {
        int kt = min(KT, 584 - k0);
        __syncthreads();
        for (int i = tid; i < kt*128; i += THREADS) wt[i] = ptw1[k0*128 + i];
        for (int i = tid; i < kt*64;  i += THREADS) ct[i] = cfw1[k0*64  + i];
        __syncthreads();
        int ch = (kt + 7) >> 3;
        int kb = min(kc*ch, kt), ke = min(kb + ch, kt);
        #pragma unroll 2
        for (int kk = kb; kk < ke; kk++) {
            int k = k0 + kk;
            ull f0 = Au[(sg*4 + 0)*PAIR_ST + k];
            ull f1 = Au[(sg*4 + 1)*PAIR_ST + k];
            ull f2 = Au[(sg*4 + 2)*PAIR_ST + k];
            ull f3 = Au[(sg*4 + 3)*PAIR_ST + k];
            float4 wp = *(const float4*)(wt + kk*128 + og*4);
            float2 wc = *(const float2*)(ct + kk*64  + og*2);
            ull w;
            w = dup2(wp.x);
            ffma2(a[0],  w, f0); ffma2(a[1],  w, f1); ffma2(a[2],  w, f2); ffma2(a[3],  w, f3);
            w = dup2(wp.y);
            ffma2(a[4],  w, f0); ffma2(a[5],  w, f1); ffma2(a[6],  w, f2); ffma2(a[7],  w, f3);
            w = dup2(wp.z);
            ffma2(a[8],  w, f0); ffma2(a[9],  w, f1); ffma2(a[10], w, f2); ffma2(a[11], w, f3);
            w = dup2(wp.w);
            ffma2(a[12], w, f0); ffma2(a[13], w, f1); ffma2(a[14], w, f2); ffma2(a[15], w, f3);
            w = dup2(wc.x);
            ffma2(a[16], w, f0); ffma2(a[17], w, f1); ffma2(a[18], w, f2); ffma2(a[19], w, f3);
            w = dup2(wc.y);
            ffma2(a[20], w, f0); ffma2(a[21], w, f1); ffma2(a[22], w, f2); ffma2(a[23], w, f3);
        }
    }
    // 2-stage reduction through X scratch (stride 25)
    const int g = sg*32 + og;          // 0..95
    __syncthreads();                   // tiles dead
    if (kc >= 4) {
        ull* sp = Xu + (size_t)((kc-4)*96 + g) * 25;
        #pragma unroll
        for (int t = 0; t < 24; t++) sp[t] = a[t];
    }
    __syncthreads();
    if (kc < 4) {
        const ull* sp = Xu + (size_t)(kc*96 + g) * 25;
        #pragma unroll
        for (int t = 0; t < 24; t++) a[t] = fadd2(a[t], sp[t]);
    }
    __syncthreads();
    if (kc >= 1 && kc < 4) {
        ull* sp = Xu + (size_t)((kc-1)*96 + g) * 25;
        #pragma unroll
        for (int t = 0; t < 24; t++) sp[t] = a[t];
    }
    __syncthreads();
    if (kc == 0) {
        #pragma unroll
        for (int c = 0; c < 3; c++) {
            const ull* sp = Xu + (size_t)(c*96 + g) * 25;
            #pragma unroll
            for (int t = 0; t < 24; t++) a[t] = fadd2(a[t], sp[t]);
        }
        #pragma unroll
        for (int i = 0; i < 4; i++) {
            int pr2 = sg*4 + i;
            #pragma unroll
            for (int j = 0; j < 4; j++) {
                float b = ptb1[og*4 + j];
                float lo, hi; unpk(a[j*4 + i], lo, hi);
                Bu[T1O + pr2*128 + og*4 + j] = pk(fmaxf(lo+b,0.f), fmaxf(hi+b,0.f));
            }
            #pragma unroll
            for (int j = 0; j < 2; j++) {
                float b = cfb1[og*2 + j];
                float lo, hi; unpk(a[(4+j)*4 + i], lo, hi);
                Bu[C1O + pr2*66 + og*2 + j] = pk(fmaxf(lo+b,0.f), fmaxf(hi+b,0.f));
            }
        }
    }
    __syncthreads();   // T1/C1 ready; X scratch dead

    // ---------- head weights -> X ----------
    for (int i = tid; i < 128*64; i += THREADS) cw[W2S + i] = ptw2[i];
    if (tid < 128) cw[W3S + tid] = ptw3[tid];
    else if (tid >= 128 && tid < 192) cw[B2SH + tid - 128] = ptb2[tid - 128];
    else if (tid == 192) { cw[B3SH] = ptb3[0]; cw[B3SH+1] = ptb3[1]; cw[CB2S] = cfb2[0]; }
    else if (tid >= 256 && tid < 320) cw[CW2S + tid - 256] = cfw2[tid - 256];
    __syncthreads();

    // ---------- pt2: 128->64, relu. thread = (pair, out) ----------
    {
        int p2  = tid >> 6;        // 0..11
        int out = tid & 63;
        ull acc = 0;
        #pragma unroll 4
        for (int k = 0; k < 128; k++) {
            ull f = Bu[T1O + p2*128 + k];          // broadcast within warp
            ffma2(acc, dup2(cw[W2S + k*64 + out]), f);
        }
        float lo, hi, b = cw[B2SH + out];
        unpk(acc, lo, hi);
        Bu[T2O + p2*66 + out] = pk(fmaxf(lo+b,0.f), fmaxf(hi+b,0.f));
    }
    __syncthreads();

    // ---------- pt3 + softmax, cf2 + sigmoid (warp-per-pair, warps 0..11) ----------
    if (wid < NPAIR) {
        int pr = wid;
        ull f0 = Bu[T2O + pr*66 + lane];
        ull f1 = Bu[T2O + pr*66 + lane + 32];
        ull g0 = Bu[C1O + pr*66 + lane];
        ull g1 = Bu[C1O + pr*66 + lane + 32];
        ull l0 = 0, l1 = 0, cc = 0;
        ffma2(l0, dup2(cw[W3S + lane*2 + 0]), f0);
        ffma2(l1, dup2(cw[W3S + lane*2 + 1]), f0);
        ffma2(l0, dup2(cw[W3S + (lane+32)*2 + 0]), f1);
        ffma2(l1, dup2(cw[W3S + (lane+32)*2 + 1]), f1);
        ffma2(cc, dup2(cw[CW2S + lane]),      g0);
        ffma2(cc, dup2(cw[CW2S + lane + 32]), g1);
        #pragma unroll
        for (int i = 16; i > 0; i >>= 1) {
            l0 = fadd2(l0, __shfl_xor_sync(0xffffffffu, l0, i));
            l1 = fadd2(l1, __shfl_xor_sync(0xffffffffu, l1, i));
            cc = fadd2(cc, __shfl_xor_sync(0xffffffffu, cc, i));
        }
        if (lane == 0) {
            int so = blockIdx.x * SPB + pr * 2;
            float l0a,l0b,l1a,l1b,ca,cb;
            unpk(l0, l0a, l0b); unpk(l1, l1a, l1b); unpk(cc, ca, cb);
            float b0 = cw[B3SH], b1 = cw[B3SH+1], bc = cw[CB2S];
            if (so < nsamp) {
                float la = l0a + b0, lb = l1a + b1;
                float m = fmaxf(la, lb);
                float e0 = expf(la - m), e1 = expf(lb - m);
                float inv = 1.f / (e0 + e1);
                gout[(size_t)so*3 + 0] = e0 * inv;
                gout[(size_t)so*3 + 1] = e1 * inv;
                gout[(size_t)so*3 + 2] = 1.f / (1.f + expf(-(ca + bc)));
            }
            if (so + 1 < nsamp) {
                float la = l0b + b0, lb = l1b + b1;
                float m = fmaxf(la, lb);
                float e0 = expf(la - m), e1 = expf(lb - m);
                float inv = 1.f / (e0 + e1);
                gout[(size_t)(so+1)*3 + 0] = e0 * inv;
                gout[(size_t)(so+1)*3 + 1] = e1 * inv;
                gout[(size_t)(so+1)*3 + 2] = 1.f / (1.f + expf(-(cb + bc)));
            }
        }
    }
}

extern "C" void kernel_launch(void* const* d_in, const int* in_sizes, int n_in,
                              void* d_out, int out_size) {
    const float* board = (const float*)d_in[0];
    const float* c1w = (const float*)d_in[2];
    const float* c1b = (const float*)d_in[3];
    const float* c2w = (const float*)d_in[4];
    const float* c2b = (const float*)d_in[5];
    const float* c3w = (const float*)d_in[6];
    const float* c3b = (const float*)d_in[7];
    const float* qp  = (const float*)d_in[8];
    const float* ptw1 = (const float*)d_in[9];
    const float* ptb1 = (const float*)d_in[10];
    const float* ptw2 = (const float*)d_in[11];
    const float* ptb2 = (const float*)d_in[12];
    const float* ptw3 = (const float*)d_in[13];
    const float* ptb3 = (const float*)d_in[14];
    const float* cfw1 = (const float*)d_in[15];
    const float* cfb1 = (const float*)d_in[16];
    const float* cfw2 = (const float*)d_in[17];
    const float* cfb2 = (const float*)d_in[18];
    float* gout = (float*)d_out;

    int nsamp = in_sizes[0] / 108;
    int blocks = (nsamp + SPB - 1) / SPB;

    cudaFuncSetAttribute(cqcnn_kernel,
                         cudaFuncAttributeMaxDynamicSharedMemorySize, SMEM_BYTES);
    cqcnn_kernel<<<blocks, THREADS, SMEM_BYTES>>>(
        board, c1w, c1b, c2w, c2b, c3w, c3b, qp,
        ptw1, ptb1, ptw2, ptb2, ptw3, ptb3,
        cfw1, cfb1, cfw2, cfb2, gout, nsamp);
}

// round 12
// speedup vs baseline: 1.0458x; 1.0458x over previous
#include <cuda_runtime.h>
#include <math.h>

typedef unsigned long long ull;
struct u2v { ull x, y; };

#define THREADS 768
#define SPB 24
#define NPAIR 12

// X region: conv weights (conv2 pre-duplicated as ull). Later FC1 reduction scratch.
// float indices:
#define W1_OFF  0          // 432
#define B1_OFF  432        // 16  -> 448 floats = 224 ull
#define W2D_U   224        // ull index: 32 rows x 145 ull = 4640 -> ends ull 4864
#define B2C_OFF 9728       // 32
#define W3_OFF  9760       // 64*289 = 18496
#define B3_OFF  28256      // 64 -> 28320 floats
#define X_FLOATS 28320
#define X_BYTES (X_FLOATS * 4)             // 113280

#define PAIR_ST 592
#define A_ULL (NPAIR * PAIR_ST)
#define A_BYTES (A_ULL * 8)                // 56832
#define B_ULL (NPAIR * 320)
#define B_BYTES (B_ULL * 8)                // 30720
#define SMEM_BYTES (X_BYTES + A_BYTES + B_BYTES)   // 200832

// B-region ull offsets after convs
#define T1O 0                    // 12*128
#define T2O (NPAIR * 128)        // 12*66
#define C1O (T2O + NPAIR * 66)   // 12*66  (ends 3120 <= 3840)

__device__ __forceinline__ ull dup2(float w) {
    ull r; unsigned u = __float_as_uint(w);
    asm("mov.b64 %0, {%1, %1};" : "=l"(r) : "r"(u));
    return r;
}
__device__ __forceinline__ ull pk(float lo, float hi) {
    ull r;
    asm("mov.b64 %0, {%1, %2};" : "=l"(r)
        : "r"(__float_as_uint(lo)), "r"(__float_as_uint(hi)));
    return r;
}
__device__ __forceinline__ void unpk(ull v, float& lo, float& hi) {
    unsigned a, b;
    asm("mov.b64 {%0, %1}, %2;" : "=r"(a), "=r"(b) : "l"(v));
    lo = __uint_as_float(a); hi = __uint_as_float(b);
}
__device__ __forceinline__ void ffma2(ull& d, ull a, ull b) {
    asm("fma.rn.f32x2 %0, %1, %2, %0;" : "+l"(d) : "l"(a), "l"(b));
}
__device__ __forceinline__ ull fadd2(ull a, ull b) {
    ull r;
    asm("add.rn.f32x2 %0, %1, %2;" : "=l"(r) : "l"(a), "l"(b));
    return r;
}
__device__ __forceinline__ ull relu2(ull v) {
    float lo, hi; unpk(v, lo, hi);
    return pk(fmaxf(lo, 0.f), fmaxf(hi, 0.f));
}
__device__ __forceinline__ void bar_pair(int pair) {
    asm volatile("bar.sync %0, 64;" :: "r"(pair + 1) : "memory");
}

// conv1: out rows YB..YB+2 for channel co
template<int YB>
__device__ __forceinline__ void conv1_half(const float* cw, const ull* Bw,
                                           ull* Aw, int co) {
    ull acc[18];
    ull bb = dup2(cw[B1_OFF + co]);
    #pragma unroll
    for (int p = 0; p < 18; p++) acc[p] = bb;
    const float* wr = cw + W1_OFF + co*27;
    #pragma unroll
    for (int ci = 0; ci < 3; ci++) {
        ull wd[9];
        #pragma unroll
        for (int t = 0; t < 9; t++) wd[t] = dup2(wr[ci*9 + t]);
        #pragma unroll
        for (int iy = YB - 1; iy <= YB + 3; iy++) {
            if (iy < 0 || iy > 5) continue;
            ull r[6];
            u2v v0 = *(const u2v*)(Bw + ci*36 + iy*6 + 0);
            u2v v1 = *(const u2v*)(Bw + ci*36 + iy*6 + 2);
            u2v v2 = *(const u2v*)(Bw + ci*36 + iy*6 + 4);
            r[0]=v0.x; r[1]=v0.y; r[2]=v1.x; r[3]=v1.y; r[4]=v2.x; r[5]=v2.y;
            #pragma unroll
            for (int dy = 0; dy < 3; dy++) {
                int y = iy + 1 - dy;
                if (y < YB || y > YB + 2) continue;
                #pragma unroll
                for (int dx = 0; dx < 3; dx++)
                    #pragma unroll
                    for (int x = 0; x < 6; x++) {
                        int xx = x + dx - 1;
                        if (xx < 0 || xx > 5) continue;
                        ffma2(acc[(y - YB)*6 + x], wd[dy*3 + dx], r[xx]);
                    }
            }
        }
    }
    #pragma unroll
    for (int ly = 0; ly < 3; ly++)
        #pragma unroll
        for (int x = 0; x < 6; x++)
            Aw[co*36 + (YB + ly)*6 + x] = relu2(acc[ly*6 + x]);
}

// conv2 rows H*3..H*3+2 for out channel lane; weights pre-duplicated ull
template<int H>
__device__ __forceinline__ void conv2_rows(const float* cw, const ull* Xu,
                                           const ull* Aw, ull* acc, int lane) {
    constexpr int YB = H * 3;
    constexpr int IY0 = (YB - 1 < 0) ? 0 : YB - 1;
    constexpr int IY1 = (YB + 3 > 5) ? 5 : YB + 3;
    ull bb = dup2(cw[B2C_OFF + lane]);
    #pragma unroll
    for (int p = 0; p < 18; p++) acc[p] = bb;
    const ull* w2 = Xu + W2D_U + lane*145;
    for (int ci = 0; ci < 16; ci++) {
        ull wd[9];
        #pragma unroll
        for (int t = 0; t < 9; t++) wd[t] = w2[ci*9 + t];
        #pragma unroll
        for (int iy = IY0; iy <= IY1; iy++) {
            ull r[6];
            u2v v0 = *(const u2v*)(Aw + ci*36 + iy*6 + 0);
            u2v v1 = *(const u2v*)(Aw + ci*36 + iy*6 + 2);
            u2v v2 = *(const u2v*)(Aw + ci*36 + iy*6 + 4);
            r[0]=v0.x; r[1]=v0.y; r[2]=v1.x; r[3]=v1.y; r[4]=v2.x; r[5]=v2.y;
            #pragma unroll
            for (int dy = 0; dy < 3; dy++) {
                int y = iy + 1 - dy;
                if (y < YB || y > YB + 2) continue;
                #pragma unroll
                for (int dx = 0; dx < 3; dx++) {
                    #pragma unroll
                    for (int x = 0; x < 6; x++) {
                        int xx = x + dx - 1;
                        if (xx < 0 || xx > 5) continue;
                        ffma2(acc[(y - YB)*6 + x], wd[dy*3 + dx], r[xx]);
                    }
                }
            }
        }
    }
}

__global__ void __launch_bounds__(THREADS, 1)
cqcnn_kernel(const float* __restrict__ gin,
             const float* __restrict__ c1w, const float* __restrict__ c1b,
             const float* __restrict__ c2w, const float* __restrict__ c2b,
             const float* __restrict__ c3w, const float* __restrict__ c3b,
             const float* __restrict__ qp,
             const float* __restrict__ ptw1, const float* __restrict__ ptb1,
             const float* __restrict__ ptw2, const float* __restrict__ ptb2,
             const float* __restrict__ ptw3, const float* __restrict__ ptb3,
             const float* __restrict__ cfw1, const float* __restrict__ cfb1,
             const float* __restrict__ cfw2, const float* __restrict__ cfb2,
             float* __restrict__ gout, int nsamp)
{
    extern __shared__ unsigned char smem[];
    float* cw = (float*)smem;                      // X (floats)
    ull*  Xu  = (ull*)smem;                        // X (ull view)
    ull*  Au  = (ull*)(smem + X_BYTES);            // per-pair feats
    ull*  Bu  = (ull*)(smem + X_BYTES + A_BYTES);  // input/pooled -> T1/T2/C1

    const int tid  = threadIdx.x;
    const int wid  = tid >> 5;
    const int lane = tid & 31;
    const int pair = wid >> 1;
    const int h    = wid & 1;

    // ---------- conv weights -> X ----------
    for (int i = tid; i < 16*27;  i += THREADS) cw[W1_OFF + i] = c1w[i];
    for (int i = tid; i < 32*144; i += THREADS)
        Xu[W2D_U + (i/144)*145 + (i%144)] = dup2(c2w[i]);   // pre-duplicated
    for (int i = tid; i < 64*288; i += THREADS)
        cw[W3_OFF + (i/288)*289 + (i%288)] = c3w[i];
    if (tid < 16) cw[B1_OFF + tid] = c1b[tid];
    else if (tid >= 64  && tid < 96)  cw[B2C_OFF + tid - 64]  = c2b[tid - 64];
    else if (tid >= 128 && tid < 192) cw[B3_OFF  + tid - 128] = c3b[tid - 128];

    // ---------- input load (each warp loads its half of the pair) ----------
    const int s0  = blockIdx.x * SPB + pair * 2;
    const int s0c = min(s0,     nsamp - 1);
    const int s1c = min(s0 + 1, nsamp - 1);
    ull* Bw = Bu + pair * 320;
    ull* Aw = Au + pair * PAIR_ST;
    for (int i = lane; i < 54; i += 32) {
        int idx = h*54 + i;
        Bw[idx] = pk(gin[(size_t)s0c * 108 + idx], gin[(size_t)s1c * 108 + idx]);
    }
    __syncthreads();   // weights + inputs visible

    // ---------- conv1 (lanes 0..15) + quantum (h=1 lanes 16..23) ----------
    if (lane < 16) {
        int co = h*8 + (lane >> 1);
        if (lane & 1) conv1_half<3>(cw, Bw, Aw, co);
        else          conv1_half<0>(cw, Bw, Aw, co);
    } else if (h == 1 && lane < 24) {
        int q = lane - 16;
        float xl, xh, nl, nh;
        unpk(Bw[q], xl, xh);
        unpk(Bw[(q + 1) & 7], nl, nh);
        float ql = 0.f, qh = 0.f;
        #pragma unroll
        for (int l = 0; l < 3; l++) {
            float r0 = qp[(l*8 + q)*3 + 0];
            float r1 = qp[(l*8 + q)*3 + 1];
            float r2 = qp[(l*8 + q)*3 + 2];
            ql = sinf(r0*xl) * cosf(r1*nl) + tanhf(r2*ql);
            qh = sinf(r0*xh) * cosf(r1*nh) + tanhf(r2*qh);
        }
        Aw[576 + q] = pk(ql, qh);
    }
    bar_pair(pair);

    // ---------- conv2 (row-half per warp) + relu + maxpool ----------
    {
        ull acc[18];
        if (h == 0) conv2_rows<0>(cw, Xu, Aw, acc, lane);
        else        conv2_rows<1>(cw, Xu, Aw, acc, lane);

        if (h == 0) {
            #pragma unroll
            for (int px = 0; px < 3; px++) {
                float a0,b0,a1,b1,a2,b2,a3,b3;
                unpk(acc[0*6 + 2*px  ], a0, b0);
                unpk(acc[0*6 + 2*px+1], a1, b1);
                unpk(acc[1*6 + 2*px  ], a2, b2);
                unpk(acc[1*6 + 2*px+1], a3, b3);
                Bw[lane*10 + px] = pk(
                    fmaxf(fmaxf(fmaxf(a0,a1), fmaxf(a2,a3)), 0.f),
                    fmaxf(fmaxf(fmaxf(b0,b1), fmaxf(b2,b3)), 0.f));
                float p0,q0,p1,q1;
                unpk(acc[2*6 + 2*px  ], p0, q0);
                unpk(acc[2*6 + 2*px+1], p1, q1);
                Bw[lane*10 + 3 + px] = pk(fmaxf(p0,p1), fmaxf(q0,q1));
            }
        }
        bar_pair(pair);
        if (h == 1) {
            #pragma unroll
            for (int px = 0; px < 3; px++) {
                float pl, ph;
                unpk(Bw[lane*10 + 3 + px], pl, ph);
                float a0,b0,a1,b1;
                unpk(acc[0*6 + 2*px  ], a0, b0);
                unpk(acc[0*6 + 2*px+1], a1, b1);
                Bw[lane*10 + 3 + px] = pk(
                    fmaxf(fmaxf(pl, fmaxf(a0,a1)), 0.f),
                    fmaxf(fmaxf(ph, fmaxf(b0,b1)), 0.f));
                float c0,d0,c1,d1,c2,d2,c3,d3;
                unpk(acc[1*6 + 2*px  ], c0, d0);
                unpk(acc[1*6 + 2*px+1], c1, d1);
                unpk(acc[2*6 + 2*px  ], c2, d2);
                unpk(acc[2*6 + 2*px+1], c3, d3);
                Bw[lane*10 + 6 + px] = pk(
                    fmaxf(fmaxf(fmaxf(c0,c1), fmaxf(c2,c3)), 0.f),
                    fmaxf(fmaxf(fmaxf(d0,d1), fmaxf(d2,d3)), 0.f));
            }
        }
    }
    bar_pair(pair);

    // ---------- conv3: 1 co per thread -> feats ----------
    {
        int co = h*32 + lane;
        ull acc[9];
        ull bb = dup2(cw[B3_OFF + co]);
        #pragma unroll
        for (int p = 0; p < 9; p++) acc[p] = bb;
        const float* w3 = cw + W3_OFF + co*289;
        for (int ci = 0; ci < 32; ci++) {
            ull r[9];
            u2v v0 = *(const u2v*)(Bw + ci*10 + 0);
            u2v v1 = *(const u2v*)(Bw + ci*10 + 2);
            u2v v2 = *(const u2v*)(Bw + ci*10 + 4);
            u2v v3 = *(const u2v*)(Bw + ci*10 + 6);
            r[0]=v0.x; r[1]=v0.y; r[2]=v1.x; r[3]=v1.y;
            r[4]=v2.x; r[5]=v2.y; r[6]=v3.x; r[7]=v3.y;
            r[8]=Bw[ci*10 + 8];
            #pragma unroll
            for (int t = 0; t < 9; t++) {
                int dy = t/3 - 1, dx = t%3 - 1;
                ull wa = dup2(w3[ci*9 + t]);
                #pragma unroll
                for (int y = 0; y < 3; y++) {
                    int yy = y + dy; if (yy < 0 || yy > 2) continue;
                    #pragma unroll
                    for (int x = 0; x < 3; x++) {
                        int xx = x + dx; if (xx < 0 || xx > 2) continue;
                        ffma2(acc[y*3+x], wa, r[yy*3+xx]);
                    }
                }
            }
        }
        #pragma unroll
        for (int p = 0; p < 9; p++)
            Aw[co*9 + p] = relu2(acc[p]);
    }
    __syncthreads();   // all feats ready; conv weights dead

    // ---------- FC1: pt1(584->128)+cf1(584->64), weights direct from global ----------
    // thread = og(lane) x sg(wid%3: pairs sg*4..+3) x kc(wid/3: k-chunk of 73)
    const int og = lane;
    const int sg = (wid % 3);
    const int kc = wid / 3;
    ull a[24];
    #pragma unroll
    for (int t = 0; t < 24; t++) a[t] = 0ull;
    {
        const ull* f0p = Au + (sg*4 + 0)*PAIR_ST;
        const ull* f1p = Au + (sg*4 + 1)*PAIR_ST;
        const ull* f2p = Au + (sg*4 + 2)*PAIR_ST;
        const ull* f3p = Au + (sg*4 + 3)*PAIR_ST;
        const float4* __restrict__ Wp = (const float4*)ptw1 + og;  // [k*32]
        const float2* __restrict__ Wc = (const float2*)cfw1 + og;  // [k*32]
        int kb = kc * 73, ke = kb + 73;
        #pragma unroll 2
        for (int k = kb; k < ke; k++) {
            float4 wp = Wp[k*32];
            float2 wc = Wc[k*32];
            ull f0 = f0p[k], f1 = f1p[k], f2 = f2p[k], f3 = f3p[k];
            ull w;
            w = dup2(wp.x);
            ffma2(a[0],  w, f0); ffma2(a[1],  w, f1); ffma2(a[2],  w, f2); ffma2(a[3],  w, f3);
            w = dup2(wp.y);
            ffma2(a[4],  w, f0); ffma2(a[5],  w, f1); ffma2(a[6],  w, f2); ffma2(a[7],  w, f3);
            w = dup2(wp.z);
            ffma2(a[8],  w, f0); ffma2(a[9],  w, f1); ffma2(a[10], w, f2); ffma2(a[11], w, f3);
            w = dup2(wp.w);
            ffma2(a[12], w, f0); ffma2(a[13], w, f1); ffma2(a[14], w, f2); ffma2(a[15], w, f3);
            w = dup2(wc.x);
            ffma2(a[16], w, f0); ffma2(a[17], w, f1); ffma2(a[18], w, f2); ffma2(a[19], w, f3);
            w = dup2(wc.y);
            ffma2(a[20], w, f0); ffma2(a[21], w, f1); ffma2(a[22], w, f2); ffma2(a[23], w, f3);
        }
    }
    // 2-stage reduction through X scratch (stride 25); conv weights dead
    const int g = sg*32 + og;          // 0..95
    if (kc >= 4) {
        ull* sp = Xu + (size_t)((kc-4)*96 + g) * 25;
        #pragma unroll
        for (int t = 0; t < 24; t++) sp[t] = a[t];
    }
    __syncthreads();
    if (kc < 4) {
        const ull* sp = Xu + (size_t)(kc*96 + g) * 25;
        #pragma unroll
        for (int t = 0; t < 24; t++) a[t] = fadd2(a[t], sp[t]);
    }
    __syncthreads();
    if (kc >= 1 && kc < 4) {
        ull* sp = Xu + (size_t)((kc-1)*96 + g) * 25;
        #pragma unroll
        for (int t = 0; t < 24; t++) sp[t] = a[t];
    }
    __syncthreads();
    if (kc == 0) {
        #pragma unroll
        for (int c = 0; c < 3; c++) {
            const ull* sp = Xu + (size_t)(c*96 + g) * 25;
            #pragma unroll
            for (int t = 0; t < 24; t++) a[t] = fadd2(a[t], sp[t]);
        }
        #pragma unroll
        for (int i = 0; i < 4; i++) {
            int pr2 = sg*4 + i;
            #pragma unroll
            for (int j = 0; j < 4; j++) {
                float b = ptb1[og*4 + j];
                float lo, hi; unpk(a[j*4 + i], lo, hi);
                Bu[T1O + pr2*128 + og*4 + j] = pk(fmaxf(lo+b,0.f), fmaxf(hi+b,0.f));
            }
            #pragma unroll
            for (int j = 0; j < 2; j++) {
                float b = cfb1[og*2 + j];
                float lo, hi; unpk(a[(4+j)*4 + i], lo, hi);
                Bu[C1O + pr2*66 + og*2 + j] = pk(fmaxf(lo+b,0.f), fmaxf(hi+b,0.f));
            }
        }
    }
    __syncthreads();   // T1/C1 ready

    // ---------- pt2: 128->64, relu; thread = (pair, out); weights direct LDG ----------
    {
        int p2  = tid >> 6;        // 0..11
        int out = tid & 63;
        const ull* t1 = Bu + T1O + p2*128;
        ull acc = 0;
        #pragma unroll 4
        for (int k = 0; k < 128; k++)
            ffma2(acc, dup2(__ldg(ptw2 + k*64 + out)), t1[k]);
        float lo, hi, b = ptb2[out];
        unpk(acc, lo, hi);
        Bu[T2O + p2*66 + out] = pk(fmaxf(lo+b,0.f), fmaxf(hi+b,0.f));
    }
    __syncthreads();

    // ---------- pt3 + softmax, cf2 + sigmoid (warps 0..11); weights direct LDG ----------
    if (wid < NPAIR) {
        int pr = wid;
        ull f0 = Bu[T2O + pr*66 + lane];
        ull f1 = Bu[T2O + pr*66 + lane + 32];
        ull g0 = Bu[C1O + pr*66 + lane];
        ull g1 = Bu[C1O + pr*66 + lane + 32];
        ull l0 = 0, l1 = 0, cc = 0;
        ffma2(l0, dup2(__ldg(ptw3 + lane*2 + 0)), f0);
        ffma2(l1, dup2(__ldg(ptw3 + lane*2 + 1)), f0);
        ffma2(l0, dup2(__ldg(ptw3 + (lane+32)*2 + 0)), f1);
        ffma2(l1, dup2(__ldg(ptw3 + (lane+32)*2 + 1)), f1);
        ffma2(cc, dup2(__ldg(cfw2 + lane)),      g0);
        ffma2(cc, dup2(__ldg(cfw2 + lane + 32)), g1);
        #pragma unroll
        for (int i = 16; i > 0; i >>= 1) {
            l0 = fadd2(l0, __shfl_xor_sync(0xffffffffu, l0, i));
            l1 = fadd2(l1, __shfl_xor_sync(0xffffffffu, l1, i));
            cc = fadd2(cc, __shfl_xor_sync(0xffffffffu, cc, i));
        }
        if (lane == 0) {
            int so = blockIdx.x * SPB + pr * 2;
            float l0a,l0b,l1a,l1b,ca,cb;
            unpk(l0, l0a, l0b); unpk(l1, l1a, l1b); unpk(cc, ca, cb);
            float b0 = ptb3[0], b1 = ptb3[1], bc = cfb2[0];
            if (so < nsamp) {
                float la = l0a + b0, lb = l1a + b1;
                float m = fmaxf(la, lb);
                float e0 = expf(la - m), e1 = expf(lb - m);
                float inv = 1.f / (e0 + e1);
                gout[(size_t)so*3 + 0] = e0 * inv;
                gout[(size_t)so*3 + 1] = e1 * inv;
                gout[(size_t)so*3 + 2] = 1.f / (1.f + expf(-(ca + bc)));
            }
            if (so + 1 < nsamp) {
                float la = l0b + b0, lb = l1b + b1;
                float m = fmaxf(la, lb);
                float e0 = expf(la - m), e1 = expf(lb - m);
                float inv = 1.f / (e0 + e1);
                gout[(size_t)(so+1)*3 + 0] = e0 * inv;
                gout[(size_t)(so+1)*3 + 1] = e1 * inv;
                gout[(size_t)(so+1)*3 + 2] = 1.f / (1.f + expf(-(cb + bc)));
            }
        }
    }
}

extern "C" void kernel_launch(void* const* d_in, const int* in_sizes, int n_in,
                              void* d_out, int out_size) {
    const float* board = (const float*)d_in[0];
    const float* c1w = (const float*)d_in[2];
    const float* c1b = (const float*)d_in[3];
    const float* c2w = (const float*)d_in[4];
    const float* c2b = (const float*)d_in[5];
    const float* c3w = (const float*)d_in[6];
    const float* c3b = (const float*)d_in[7];
    const float* qp  = (const float*)d_in[8];
    const float* ptw1 = (const float*)d_in[9];
    const float* ptb1 = (const float*)d_in[10];
    const float* ptw2 = (const float*)d_in[11];
    const float* ptb2 = (const float*)d_in[12];
    const float* ptw3 = (const float*)d_in[13];
    const float* ptb3 = (const float*)d_in[14];
    const float* cfw1 = (const float*)d_in[15];
    const float* cfb1 = (const float*)d_in[16];
    const float* cfw2 = (const float*)d_in[17];
    const float* cfb2 = (const float*)d_in[18];
    float* gout = (float*)d_out;

    int nsamp = in_sizes[0] / 108;
    int blocks = (nsamp + SPB - 1) / SPB;

    cudaFuncSetAttribute(cqcnn_kernel,
                         cudaFuncAttributeMaxDynamicSharedMemorySize, SMEM_BYTES);
    cqcnn_kernel<<<blocks, THREADS, SMEM_BYTES>>>(
        board, c1w, c1b, c2w, c2b, c3w, c3b, qp,
        ptw1, ptb1, ptw2, ptb2, ptw3, ptb3,
        cfw1, cfb1, cfw2, cfb2, gout, nsamp);
}

// round 16
// speedup vs baseline: 1.2623x; 1.2070x over previous
#include <cuda_runtime.h>
#include <math.h>

typedef unsigned long long ull;
struct u2v { ull x, y; };

#define THREADS 512
#define SPB 32
#define NPAIR 16

// X region: conv weights (conv2 pre-duplicated as ull). Later FC1 reduction scratch.
#define W1_OFF  0          // 432 floats
#define B1_OFF  432        // 16 -> 448 floats = 224 ull
#define W2D_U   224        // ull idx: 32 x 145 ull -> ends ull 4864
#define B2C_OFF 9728       // 32 floats
#define W3_OFF  9760       // 64*289
#define B3_OFF  28256      // 64 -> 28320
#define X_FLOATS 28320
#define X_BYTES (X_FLOATS * 4)             // 113280

#define PAIR_ST 592
#define A_ULL (NPAIR * PAIR_ST)
#define A_BYTES (A_ULL * 8)                // 75776
#define B_ULL (NPAIR * 320)
#define B_BYTES (B_ULL * 8)                // 40960
#define SMEM_BYTES (X_BYTES + A_BYTES + B_BYTES)   // 230016

// B-region ull offsets after convs
#define T1O 0                    // 16*128
#define T2O (NPAIR * 128)        // 16*66
#define C1O (T2O + NPAIR * 66)   // 16*66 (ends 4160 <= 5120)

__device__ __forceinline__ ull dup2(float w) {
    ull r; unsigned u = __float_as_uint(w);
    asm("mov.b64 %0, {%1, %1};" : "=l"(r) : "r"(u));
    return r;
}
__device__ __forceinline__ ull pk(float lo, float hi) {
    ull r;
    asm("mov.b64 %0, {%1, %2};" : "=l"(r)
        : "r"(__float_as_uint(lo)), "r"(__float_as_uint(hi)));
    return r;
}
__device__ __forceinline__ void unpk(ull v, float& lo, float& hi) {
    unsigned a, b;
    asm("mov.b64 {%0, %1}, %2;" : "=r"(a), "=r"(b) : "l"(v));
    lo = __uint_as_float(a); hi = __uint_as_float(b);
}
__device__ __forceinline__ void ffma2(ull& d, ull a, ull b) {
    asm("fma.rn.f32x2 %0, %1, %2, %0;" : "+l"(d) : "l"(a), "l"(b));
}
__device__ __forceinline__ ull fadd2(ull a, ull b) {
    ull r;
    asm("add.rn.f32x2 %0, %1, %2;" : "=l"(r) : "l"(a), "l"(b));
    return r;
}
__device__ __forceinline__ ull relu2(ull v) {
    float lo, hi; unpk(v, lo, hi);
    return pk(fmaxf(lo, 0.f), fmaxf(hi, 0.f));
}

// conv1: out rows YB..YB+2 for channel co
template<int YB>
__device__ __forceinline__ void conv1_half(const float* cw, const ull* Bw,
                                           ull* Aw, int co) {
    ull acc[18];
    ull bb = dup2(cw[B1_OFF + co]);
    #pragma unroll
    for (int p = 0; p < 18; p++) acc[p] = bb;
    const float* wr = cw + W1_OFF + co*27;
    #pragma unroll
    for (int ci = 0; ci < 3; ci++) {
        ull wd[9];
        #pragma unroll
        for (int t = 0; t < 9; t++) wd[t] = dup2(wr[ci*9 + t]);
        #pragma unroll
        for (int iy = YB - 1; iy <= YB + 3; iy++) {
            if (iy < 0 || iy > 5) continue;
            ull r[6];
            u2v v0 = *(const u2v*)(Bw + ci*36 + iy*6 + 0);
            u2v v1 = *(const u2v*)(Bw + ci*36 + iy*6 + 2);
            u2v v2 = *(const u2v*)(Bw + ci*36 + iy*6 + 4);
            r[0]=v0.x; r[1]=v0.y; r[2]=v1.x; r[3]=v1.y; r[4]=v2.x; r[5]=v2.y;
            #pragma unroll
            for (int dy = 0; dy < 3; dy++) {
                int y = iy + 1 - dy;
                if (y < YB || y > YB + 2) continue;
                #pragma unroll
                for (int dx = 0; dx < 3; dx++)
                    #pragma unroll
                    for (int x = 0; x < 6; x++) {
                        int xx = x + dx - 1;
                        if (xx < 0 || xx > 5) continue;
                        ffma2(acc[(y - YB)*6 + x], wd[dy*3 + dx], r[xx]);
                    }
            }
        }
    }
    #pragma unroll
    for (int ly = 0; ly < 3; ly++)
        #pragma unroll
        for (int x = 0; x < 6; x++)
            Aw[co*36 + (YB + ly)*6 + x] = relu2(acc[ly*6 + x]);
}

__global__ void __launch_bounds__(THREADS, 1)
cqcnn_kernel(const float* __restrict__ gin,
             const float* __restrict__ c1w, const float* __restrict__ c1b,
             const float* __restrict__ c2w, const float* __restrict__ c2b,
             const float* __restrict__ c3w, const float* __restrict__ c3b,
             const float* __restrict__ qp,
             const float* __restrict__ ptw1, const float* __restrict__ ptb1,
             const float* __restrict__ ptw2, const float* __restrict__ ptb2,
             const float* __restrict__ ptw3, const float* __restrict__ ptb3,
             const float* __restrict__ cfw1, const float* __restrict__ cfb1,
             const float* __restrict__ cfw2, const float* __restrict__ cfb2,
             float* __restrict__ gout, int nsamp)
{
    extern __shared__ unsigned char smem[];
    float* cw = (float*)smem;                      // X (floats)
    ull*  Xu  = (ull*)smem;                        // X (ull view)
    ull*  Au  = (ull*)(smem + X_BYTES);            // per-pair feats
    ull*  Bu  = (ull*)(smem + X_BYTES + A_BYTES);  // input/pooled -> T1/T2/C1

    const int tid  = threadIdx.x;
    const int wid  = tid >> 5;
    const int lane = tid & 31;

    // ---------- conv weights -> X ----------
    for (int i = tid; i < 16*27;  i += THREADS) cw[W1_OFF + i] = c1w[i];
    for (int i = tid; i < 32*144; i += THREADS)
        Xu[W2D_U + (i/144)*145 + (i%144)] = dup2(c2w[i]);   // pre-duplicated
    for (int i = tid; i < 64*288; i += THREADS)
        cw[W3_OFF + (i/288)*289 + (i%288)] = c3w[i];
    if (tid < 16) cw[B1_OFF + tid] = c1b[tid];
    else if (tid >= 64  && tid < 96)  cw[B2C_OFF + tid - 64]  = c2b[tid - 64];
    else if (tid >= 128 && tid < 192) cw[B3_OFF  + tid - 128] = c3b[tid - 128];

    // ---------- per-warp sample pair load ----------
    const int s0  = blockIdx.x * SPB + wid * 2;
    const int s0c = min(s0,     nsamp - 1);
    const int s1c = min(s0 + 1, nsamp - 1);
    ull* Bw = Bu + wid * 320;      // input(108), later pooled (32 ch x stride 10)
    ull* Aw = Au + wid * PAIR_ST;  // conv1 acts / feats
    for (int i = lane; i < 108; i += 32)
        Bw[i] = pk(gin[(size_t)s0c * 108 + i], gin[(size_t)s1c * 108 + i]);
    __syncthreads();   // weights visible (barrier #1)

    // ================= barrier-free warp-private section =================

    // ---------- quantum feature -> feats[576..583] ----------
    if (lane < 8) {
        float xl, xh, nl, nh;
        unpk(Bw[lane], xl, xh);
        unpk(Bw[(lane + 1) & 7], nl, nh);
        float ql = 0.f, qh = 0.f;
        #pragma unroll
        for (int l = 0; l < 3; l++) {
            float r0 = qp[(l*8 + lane)*3 + 0];
            float r1 = qp[(l*8 + lane)*3 + 1];
            float r2 = qp[(l*8 + lane)*3 + 2];
            ql = sinf(r0*xl) * cosf(r1*nl) + tanhf(r2*ql);
            qh = sinf(r0*xh) * cosf(r1*nh) + tanhf(r2*qh);
        }
        Aw[576 + lane] = pk(ql, qh);
    }

    // ---------- conv1: lane = (co, row-half) ----------
    {
        int co = lane >> 1;
        if (lane & 1) conv1_half<3>(cw, Bw, Aw, co);
        else          conv1_half<0>(cw, Bw, Aw, co);
    }
    __syncwarp();

    // ---------- conv2: 16->32 + relu + maxpool -> Bw[ch*10 + p] ----------
    {
        ull acc[36];
        ull bb = dup2(cw[B2C_OFF + lane]);
        #pragma unroll
        for (int p = 0; p < 36; p++) acc[p] = bb;
        const ull* w2 = Xu + W2D_U + lane*145;     // pre-duplicated ull weights
        for (int ci = 0; ci < 16; ci++) {
            ull wd[9];
            #pragma unroll
            for (int t = 0; t < 9; t++) wd[t] = w2[ci*9 + t];
            #pragma unroll
            for (int iy = 0; iy < 6; iy++) {
                ull r[6];
                u2v v0 = *(const u2v*)(Aw + ci*36 + iy*6 + 0);
                u2v v1 = *(const u2v*)(Aw + ci*36 + iy*6 + 2);
                u2v v2 = *(const u2v*)(Aw + ci*36 + iy*6 + 4);
                r[0]=v0.x; r[1]=v0.y; r[2]=v1.x; r[3]=v1.y; r[4]=v2.x; r[5]=v2.y;
                #pragma unroll
                for (int dy = 0; dy < 3; dy++) {
                    int y = iy + 1 - dy;
                    if (y < 0 || y > 5) continue;
                    #pragma unroll
                    for (int dx = 0; dx < 3; dx++) {
                        #pragma unroll
                        for (int x = 0; x < 6; x++) {
                            int xx = x + dx - 1;
                            if (xx < 0 || xx > 5) continue;
                            ffma2(acc[y*6 + x], wd[dy*3 + dx], r[xx]);
                        }
                    }
                }
            }
        }
        #pragma unroll
        for (int py = 0; py < 3; py++)
            #pragma unroll
            for (int px = 0; px < 3; px++) {
                float a0,b0,a1,b1,a2,b2,a3,b3;
                unpk(acc[(2*py)*6   + 2*px  ], a0, b0);
                unpk(acc[(2*py)*6   + 2*px+1], a1, b1);
                unpk(acc[(2*py+1)*6 + 2*px  ], a2, b2);
                unpk(acc[(2*py+1)*6 + 2*px+1], a3, b3);
                float lo = fmaxf(fmaxf(fmaxf(a0,a1), fmaxf(a2,a3)), 0.f);
                float hi = fmaxf(fmaxf(fmaxf(b0,b1), fmaxf(b2,b3)), 0.f);
                Bw[lane*10 + py*3 + px] = pk(lo, hi);
            }
    }
    __syncwarp();

    // ---------- conv3: 32->64, 3x3, pad1, relu -> feats[0..575] ----------
    {
        ull acc0[9], acc1[9];
        ull b30 = dup2(cw[B3_OFF + lane]);
        ull b31 = dup2(cw[B3_OFF + lane + 32]);
        #pragma unroll
        for (int p = 0; p < 9; p++) { acc0[p] = b30; acc1[p] = b31; }
        const float* w3a = cw + W3_OFF + lane*289;
        const float* w3b = cw + W3_OFF + (lane+32)*289;
        for (int ci = 0; ci < 32; ci++) {
            ull r[9];
            u2v v0 = *(const u2v*)(Bw + ci*10 + 0);
            u2v v1 = *(const u2v*)(Bw + ci*10 + 2);
            u2v v2 = *(const u2v*)(Bw + ci*10 + 4);
            u2v v3 = *(const u2v*)(Bw + ci*10 + 6);
            r[0]=v0.x; r[1]=v0.y; r[2]=v1.x; r[3]=v1.y;
            r[4]=v2.x; r[5]=v2.y; r[6]=v3.x; r[7]=v3.y;
            r[8]=Bw[ci*10 + 8];
            #pragma unroll
            for (int t = 0; t < 9; t++) {
                int dy = t/3 - 1, dx = t%3 - 1;
                ull wa = dup2(w3a[ci*9 + t]);
                ull wb = dup2(w3b[ci*9 + t]);
                #pragma unroll
                for (int y = 0; y < 3; y++) {
                    int yy = y + dy; if (yy < 0 || yy > 2) continue;
                    #pragma unroll
                    for (int x = 0; x < 3; x++) {
                        int xx = x + dx; if (xx < 0 || xx > 2) continue;
                        ffma2(acc0[y*3+x], wa, r[yy*3+xx]);
                        ffma2(acc1[y*3+x], wb, r[yy*3+xx]);
                    }
                }
            }
        }
        #pragma unroll
        for (int p = 0; p < 9; p++) {
            Aw[lane*9 + p]      = relu2(acc0[p]);
            Aw[(lane+32)*9 + p] = relu2(acc1[p]);
        }
    }
    __syncthreads();   // feats ready for all pairs; X conv weights dead (barrier #2)

    // ---------- FC1: pt1(584->128)+cf1(584->64), direct-LDG weights ----------
    // thread = og(lane) x sg((tid>>5)&3: pairs sg*4..+3) x kc(tid>>7: 146 k's)
    const int og = lane;
    const int sg = (tid >> 5) & 3;
    const int kc = tid >> 7;
    ull a[24];
    #pragma unroll
    for (int t = 0; t < 24; t++) a[t] = 0ull;
    {
        const ull* f0p = Au + (sg*4 + 0)*PAIR_ST;
        const ull* f1p = Au + (sg*4 + 1)*PAIR_ST;
        const ull* f2p = Au + (sg*4 + 2)*PAIR_ST;
        const ull* f3p = Au + (sg*4 + 3)*PAIR_ST;
        const float4* __restrict__ Wp = (const float4*)ptw1 + og;  // [k*32]
        const float2* __restrict__ Wc = (const float2*)cfw1 + og;  // [k*32]
        int kb = kc * 146, ke = kb + 146;
        #pragma unroll 2
        for (int k = kb; k < ke; k++) {
            float4 wp = Wp[k*32];
            float2 wc = Wc[k*32];
            ull f0 = f0p[k], f1 = f1p[k], f2 = f2p[k], f3 = f3p[k];
            ull w;
            w = dup2(wp.x);
            ffma2(a[0],  w, f0); ffma2(a[1],  w, f1); ffma2(a[2],  w, f2); ffma2(a[3],  w, f3);
            w = dup2(wp.y);
            ffma2(a[4],  w, f0); ffma2(a[5],  w, f1); ffma2(a[6],  w, f2); ffma2(a[7],  w, f3);
            w = dup2(wp.z);
            ffma2(a[8],  w, f0); ffma2(a[9],  w, f1); ffma2(a[10], w, f2); ffma2(a[11], w, f3);
            w = dup2(wp.w);
            ffma2(a[12], w, f0); ffma2(a[13], w, f1); ffma2(a[14], w, f2); ffma2(a[15], w, f3);
            w = dup2(wc.x);
            ffma2(a[16], w, f0); ffma2(a[17], w, f1); ffma2(a[18], w, f2); ffma2(a[19], w, f3);
            w = dup2(wc.y);
            ffma2(a[20], w, f0); ffma2(a[21], w, f1); ffma2(a[22], w, f2); ffma2(a[23], w, f3);
        }
    }
    // reduction through X scratch (conv weights dead since barrier #2)
    const int g = sg*32 + og;          // 0..127
    if (kc > 0) {
        ull* sp = Xu + (size_t)((kc-1)*128 + g) * 25;
        #pragma unroll
        for (int t = 0; t < 24; t++) sp[t] = a[t];
    }
    __syncthreads();   // (barrier #3)
    if (kc == 0) {
        #pragma unroll
        for (int c = 0; c < 3; c++) {
            const ull* sp = Xu + (size_t)(c*128 + g) * 25;
            #pragma unroll
            for (int t = 0; t < 24; t++) a[t] = fadd2(a[t], sp[t]);
        }
        #pragma unroll
        for (int i = 0; i < 4; i++) {
            int pr2 = sg*4 + i;
            #pragma unroll
            for (int j = 0; j < 4; j++) {
                float b = ptb1[og*4 + j];
                float lo, hi; unpk(a[j*4 + i], lo, hi);
                Bu[T1O + pr2*128 + og*4 + j] = pk(fmaxf(lo+b,0.f), fmaxf(hi+b,0.f));
            }
            #pragma unroll
            for (int j = 0; j < 2; j++) {
                float b = cfb1[og*2 + j];
                float lo, hi; unpk(a[(4+j)*4 + i], lo, hi);
                Bu[C1O + pr2*66 + og*2 + j] = pk(fmaxf(lo+b,0.f), fmaxf(hi+b,0.f));
            }
        }
    }
    __syncthreads();   // T1/C1 ready (barrier #4)

    // ---------- pt2: 128->64, relu; warp-per-pair, direct-LDG weights ----------
    const int pr = wid;
    {
        const ull* t1 = Bu + T1O + pr*128;
        ull a0 = 0, a1 = 0;
        #pragma unroll 4
        for (int k = 0; k < 128; k++) {
            ull f = t1[k];
            ffma2(a0, dup2(__ldg(ptw2 + k*64 + lane)),      f);
            ffma2(a1, dup2(__ldg(ptw2 + k*64 + lane + 32)), f);
        }
        float lo, hi, b;
        b = ptb2[lane];      unpk(a0, lo, hi);
        Bu[T2O + pr*66 + lane]      = pk(fmaxf(lo+b,0.f), fmaxf(hi+b,0.f));
        b = ptb2[lane + 32]; unpk(a1, lo, hi);
        Bu[T2O + pr*66 + lane + 32] = pk(fmaxf(lo+b,0.f), fmaxf(hi+b,0.f));
    }
    __syncwarp();

    // ---------- pt3 + softmax, cf2 + sigmoid ----------
    {
        ull f0 = Bu[T2O + pr*66 + lane];
        ull f1 = Bu[T2O + pr*66 + lane + 32];
        ull g0 = Bu[C1O + pr*66 + lane];
        ull g1 = Bu[C1O + pr*66 + lane + 32];
        ull l0 = 0, l1 = 0, cc = 0;
        ffma2(l0, dup2(__ldg(ptw3 + lane*2 + 0)), f0);
        ffma2(l1, dup2(__ldg(ptw3 + lane*2 + 1)), f0);
        ffma2(l0, dup2(__ldg(ptw3 + (lane+32)*2 + 0)), f1);
        ffma2(l1, dup2(__ldg(ptw3 + (lane+32)*2 + 1)), f1);
        ffma2(cc, dup2(__ldg(cfw2 + lane)),      g0);
        ffma2(cc, dup2(__ldg(cfw2 + lane + 32)), g1);
        #pragma unroll
        for (int i = 16; i > 0; i >>= 1) {
            l0 = fadd2(l0, __shfl_xor_sync(0xffffffffu, l0, i));
            l1 = fadd2(l1, __shfl_xor_sync(0xffffffffu, l1, i));
            cc = fadd2(cc, __shfl_xor_sync(0xffffffffu, cc, i));
        }
        if (lane == 0) {
            float l0a,l0b,l1a,l1b,ca,cb;
            unpk(l0, l0a, l0b); unpk(l1, l1a, l1b); unpk(cc, ca, cb);
            float b0 = ptb3[0], b1 = ptb3[1], bc = cfb2[0];
            if (s0 < nsamp) {
                float la = l0a + b0, lb = l1a + b1;
                float m = fmaxf(la, lb);
                float e0 = expf(la - m), e1 = expf(lb - m);
                float inv = 1.f / (e0 + e1);
                gout[(size_t)s0*3 + 0] = e0 * inv;
                gout[(size_t)s0*3 + 1] = e1 * inv;
                gout[(size_t)s0*3 + 2] = 1.f / (1.f + expf(-(ca + bc)));
            }
            if (s0 + 1 < nsamp) {
                float la = l0b + b0, lb = l1b + b1;
                float m = fmaxf(la, lb);
                float e0 = expf(la - m), e1 = expf(lb - m);
                float inv = 1.f / (e0 + e1);
                gout[(size_t)(s0+1)*3 + 0] = e0 * inv;
                gout[(size_t)(s0+1)*3 + 1] = e1 * inv;
                gout[(size_t)(s0+1)*3 + 2] = 1.f / (1.f + expf(-(cb + bc)));
            }
        }
    }
}

extern "C" void kernel_launch(void* const* d_in, const int* in_sizes, int n_in,
                              void* d_out, int out_size) {
    const float* board = (const float*)d_in[0];
    const float* c1w = (const float*)d_in[2];
    const float* c1b = (const float*)d_in[3];
    const float* c2w = (const float*)d_in[4];
    const float* c2b = (const float*)d_in[5];
    const float* c3w = (const float*)d_in[6];
    const float* c3b = (const float*)d_in[7];
    const float* qp  = (const float*)d_in[8];
    const float* ptw1 = (const float*)d_in[9];
    const float* ptb1 = (const float*)d_in[10];
    const float* ptw2 = (const float*)d_in[11];
    const float* ptb2 = (const float*)d_in[12];
    const float* ptw3 = (const float*)d_in[13];
    const float* ptb3 = (const float*)d_in[14];
    const float* cfw1 = (const float*)d_in[15];
    const float* cfb1 = (const float*)d_in[16];
    const float* cfw2 = (const float*)d_in[17];
    const float* cfb2 = (const float*)d_in[18];
    float* gout = (float*)d_out;

    int nsamp = in_sizes[0] / 108;
    int blocks = (nsamp + SPB - 1) / SPB;

    cudaFuncSetAttribute(cqcnn_kernel,
                         cudaFuncAttributeMaxDynamicSharedMemorySize, SMEM_BYTES);
    cqcnn_kernel<<<blocks, THREADS, SMEM_BYTES>>>(
        board, c1w, c1b, c2w, c2b, c3w, c3b, qp,
        ptw1, ptb1, ptw2, ptb2, ptw3, ptb3,
        cfw1, cfb1, cfw2, cfb2, gout, nsamp);
}